// round 5
// baseline (speedup 1.0000x reference)
#include <cuda_runtime.h>

// Inputs (metadata order):
// 0: user_id  int32 [16384]
// 1: item_id  int32 [16384]
// 2: category int32 [16384]
// 3: emb_user f32 [100000]
// 4: emb_item f32 [50000]
// 5: emb_cat  f32 [1000]
// 6: cross_w  f32 [150000000]
// out: f32 [16384]
//
// out[i] = emb_user[u] + emb_item[it] + emb_cat[c]
//        + cross_w[u*1000 + c] + cross_w[1e8 + it*1000 + c]
//
// Latency-bound micro-kernel at the graph-replay overhead floor.
// R3: 4 elements/thread — int4 index loads (1 LDG.128 per array instead
// of 4 LDG.32), float4 store (1 STG.128), MLP=20 gathers per thread.
// 4096 threads = 32 CTAs x 128 threads, single wave.

#define D_CAT 1000
#define OFF_IC 100000000

__global__ void __launch_bounds__(128, 1)
wide_kernel(const int4* __restrict__ user_id,
            const int4* __restrict__ item_id,
            const int4* __restrict__ category,
            const float* __restrict__ emb_user,
            const float* __restrict__ emb_item,
            const float* __restrict__ emb_cat,
            const float* __restrict__ cross_w,
            float4* __restrict__ out,
            int n4) {
    int i = blockIdx.x * 128 + threadIdx.x;
    if (i >= n4) return;

    // Phase 1: 3 coalesced 128-bit index loads (12 indices)
    int4 u4 = __ldg(&user_id[i]);
    int4 t4 = __ldg(&item_id[i]);
    int4 c4 = __ldg(&category[i]);

    // Phase 2: 20 independent gathers, all issued before any consumption
    float au0 = __ldg(&emb_user[u4.x]);
    float au1 = __ldg(&emb_user[u4.y]);
    float au2 = __ldg(&emb_user[u4.z]);
    float au3 = __ldg(&emb_user[u4.w]);

    float ai0 = __ldg(&emb_item[t4.x]);
    float ai1 = __ldg(&emb_item[t4.y]);
    float ai2 = __ldg(&emb_item[t4.z]);
    float ai3 = __ldg(&emb_item[t4.w]);

    float ac0 = __ldg(&emb_cat[c4.x]);
    float ac1 = __ldg(&emb_cat[c4.y]);
    float ac2 = __ldg(&emb_cat[c4.z]);
    float ac3 = __ldg(&emb_cat[c4.w]);

    float uc0 = __ldg(&cross_w[u4.x * D_CAT + c4.x]);
    float uc1 = __ldg(&cross_w[u4.y * D_CAT + c4.y]);
    float uc2 = __ldg(&cross_w[u4.z * D_CAT + c4.z]);
    float uc3 = __ldg(&cross_w[u4.w * D_CAT + c4.w]);

    float ic0 = __ldg(&cross_w[OFF_IC + t4.x * D_CAT + c4.x]);
    float ic1 = __ldg(&cross_w[OFF_IC + t4.y * D_CAT + c4.y]);
    float ic2 = __ldg(&cross_w[OFF_IC + t4.z * D_CAT + c4.z]);
    float ic3 = __ldg(&cross_w[OFF_IC + t4.w * D_CAT + c4.w]);

    float4 r;
    r.x = (au0 + ai0) + (ac0 + uc0) + ic0;
    r.y = (au1 + ai1) + (ac1 + uc1) + ic1;
    r.z = (au2 + ai2) + (ac2 + uc2) + ic2;
    r.w = (au3 + ai3) + (ac3 + uc3) + ic3;
    out[i] = r;
}

extern "C" void kernel_launch(void* const* d_in, const int* in_sizes, int n_in,
                              void* d_out, int out_size) {
    const int4* user_id  = (const int4*)d_in[0];
    const int4* item_id  = (const int4*)d_in[1];
    const int4* category = (const int4*)d_in[2];
    const float* emb_user = (const float*)d_in[3];
    const float* emb_item = (const float*)d_in[4];
    const float* emb_cat  = (const float*)d_in[5];
    const float* cross_w  = (const float*)d_in[6];
    float4* out = (float4*)d_out;
    int n4 = in_sizes[0] / 4;  // 4096
    int threads = 128;
    int blocks = (n4 + threads - 1) / threads;  // 32
    wide_kernel<<<blocks, threads>>>(user_id, item_id, category,
                                     emb_user, emb_item, emb_cat, cross_w,
                                     out, n4);
}

// round 7
// speedup vs baseline: 1.0909x; 1.0909x over previous
#include <cuda_runtime.h>

// Inputs (metadata order):
// 0: user_id  int32 [16384]
// 1: item_id  int32 [16384]
// 2: category int32 [16384]
// 3: emb_user f32 [100000]
// 4: emb_item f32 [50000]
// 5: emb_cat  f32 [1000]
// 6: cross_w  f32 [150000000]
// out: f32 [16384]
//
// out[i] = emb_user[u] + emb_item[it] + emb_cat[c]
//        + cross_w[u*1000 + c] + cross_w[1e8 + it*1000 + c]
//
// Converged design (R1-R5 evidence): latency-bound micro-kernel at the
// graph-replay floor. Max parallelism wins: 1 elem/thread, 16384 threads,
// 512 warps. Vectorization (4x/thread) REGRESSED (-0.3us) by cutting warp
// count. This round: minimal body — no bounds check (16384 == 128*128),
// int32 index math, 5 independent gathers, nothing else.

#define D_CAT 1000
#define OFF_IC 100000000

__global__ void __launch_bounds__(128, 1)
wide_kernel(const int* __restrict__ user_id,
            const int* __restrict__ item_id,
            const int* __restrict__ category,
            const float* __restrict__ emb_user,
            const float* __restrict__ emb_item,
            const float* __restrict__ emb_cat,
            const float* __restrict__ cross_w,
            float* __restrict__ out) {
    int i = blockIdx.x * 128 + threadIdx.x;  // exact cover, no bounds check
    // 3 coalesced index loads
    int u  = user_id[i];
    int it = item_id[i];
    int c  = category[i];
    // int32 index math (max idx ~1.5e8 < 2^31)
    int idx_uc = u * D_CAT + c;
    int idx_ic = OFF_IC + it * D_CAT + c;
    // 5 independent gathers — issued back-to-back, latency overlapped
    float a = __ldg(&emb_user[u]);
    float b = __ldg(&emb_item[it]);
    float d = __ldg(&emb_cat[c]);
    float e = __ldg(&cross_w[idx_uc]);
    float f = __ldg(&cross_w[idx_ic]);
    out[i] = (a + b) + (d + e) + f;
}

extern "C" void kernel_launch(void* const* d_in, const int* in_sizes, int n_in,
                              void* d_out, int out_size) {
    const int* user_id  = (const int*)d_in[0];
    const int* item_id  = (const int*)d_in[1];
    const int* category = (const int*)d_in[2];
    const float* emb_user = (const float*)d_in[3];
    const float* emb_item = (const float*)d_in[4];
    const float* emb_cat  = (const float*)d_in[5];
    const float* cross_w  = (const float*)d_in[6];
    float* out = (float*)d_out;
    int n = in_sizes[0];              // 16384
    int threads = 128;
    int blocks = n / threads;         // 128, exact
    wide_kernel<<<blocks, threads>>>(user_id, item_id, category,
                                     emb_user, emb_item, emb_cat, cross_w,
                                     out);
}